// round 5
// baseline (speedup 1.0000x reference)
#include <cuda_runtime.h>

#define J 256          // nb_features
#define D 64           // head_dim
#define M_TILE 64      // tokens per block-tile
#define PITCH 68       // row pitch in floats (272 B, bank offset 4/row)
#define THREADS 256
#define GRID 148       // persistent, 1 block/SM

__device__ __forceinline__ void lds_v2u64(unsigned a,
                                          unsigned long long& v0,
                                          unsigned long long& v1) {
    asm("ld.shared.v2.u64 {%0, %1}, [%2];" : "=l"(v0), "=l"(v1) : "r"(a));
}

__device__ __forceinline__ void ffma2(unsigned long long& d,
                                      unsigned long long a,
                                      unsigned long long b) {
    asm("fma.rn.f32x2 %0, %1, %2, %0;" : "+l"(d) : "l"(a), "l"(b));
}

__device__ __forceinline__ void unpack2(unsigned long long v, float& lo, float& hi) {
    asm("mov.b64 {%0, %1}, %2;" : "=f"(lo), "=f"(hi) : "l"(v));
}

__global__ __launch_bounds__(THREADS, 1)
void performer_kernel(const float* __restrict__ x,
                      const float* __restrict__ proj,
                      float* __restrict__ out,
                      int n_tiles) {
    extern __shared__ float sm[];
    // layout: ps [J][PITCH] (row-permuted), xs [M_TILE][PITCH], sdiag [M_TILE]
    float* ps    = sm;
    float* xs    = sm + J * PITCH;
    float* sdiag = xs + M_TILE * PITCH;

    const int tid = threadIdx.x;

    const float NORM  = 0.3535533905932738f;  // 64^-0.25
    const float RATIO = 0.0625f;              // 256^-0.5
    const float EPSV  = 1e-4f;

    // ---- stage projection ONCE, pre-scaled, rows permuted s(j)=(j&7)*32+(j>>3) ----
    #pragma unroll
    for (int r = 0; r < (J * D) / (THREADS * 4); r++) {   // 16 float4/thread
        int f  = tid + r * THREADS;                        // float4 index
        int j  = f >> 4;                                   // feature row
        int k0 = (f & 15) << 2;
        int s  = ((j & 7) << 5) | (j >> 3);
        float4 v = reinterpret_cast<const float4*>(proj)[f];
        v.x *= NORM; v.y *= NORM; v.z *= NORM; v.w *= NORM;
        *reinterpret_cast<float4*>(ps + s * PITCH + k0) = v;
    }

    // thread -> register-tile mapping: 8 tokens x 8 features
    const int lane = tid & 31;
    const int w    = tid >> 5;           // 0..7
    const int tg   = lane & 7;           // token group: tokens tg + 8*i
    const int jgl  = lane >> 3;          // 0..3
    const int jg   = (w << 2) + jgl;     // 0..31 ; features j = jg*8 + m
    const int j0   = jg << 3;            // first of 8 consecutive features

    unsigned sbase;
    asm("{ .reg .u64 t; cvta.to.shared.u64 t, %1; cvt.u32.u64 %0, t; }"
        : "=r"(sbase) : "l"(sm));
    // pv row for feature (jg, m): s = m*32 + jg  -> per instr lanes hit 4 consecutive rows
    const unsigned pbase = sbase + (unsigned)(jg * PITCH) * 4u;
    const unsigned xs_a  = sbase + (unsigned)(J * PITCH) * 4u;
    const unsigned xbase = xs_a + (unsigned)(tg * PITCH) * 4u;

    for (int tile = blockIdx.x; tile < n_tiles; tile += GRID) {
        const int m0 = tile * M_TILE;
        __syncthreads();   // prior tile's readers done before xs overwrite

        // ---- stage x tile, coalesced float4, identity rows ----
        const float* xblk = x + (size_t)m0 * D;
        #pragma unroll
        for (int r = 0; r < (M_TILE * D) / (THREADS * 4); r++) {  // 4 float4/thread
            int f  = tid + r * THREADS;
            int t  = f >> 4;
            int k0 = (f & 15) << 2;
            *reinterpret_cast<float4*>(xs + t * PITCH + k0) =
                reinterpret_cast<const float4*>(xblk)[f];
        }
        __syncthreads();

        // ---- diag = 0.5*||x||^2 : 4 lanes/token (16 elems each), butterfly ----
        {
            const int t  = tid >> 2;
            const int k0 = (tid & 3) * 16;
            float s = 0.f;
            #pragma unroll
            for (int k = 0; k < 16; k++) {
                float v = xs[t * PITCH + k0 + k];
                s += v * v;
            }
            s += __shfl_xor_sync(0xFFFFFFFFu, s, 2);
            s += __shfl_xor_sync(0xFFFFFFFFu, s, 1);
            if ((tid & 3) == 0) sdiag[t] = 0.5f * s;
        }
        __syncthreads();

        // ---- main loop: 8 tokens x 8 features, f32x2 along K ----
        unsigned long long acc[8][8];
        #pragma unroll
        for (int i = 0; i < 8; i++)
            #pragma unroll
            for (int m = 0; m < 8; m++) acc[i][m] = 0ull;

        #pragma unroll
        for (int kq = 0; kq < D / 4; kq++) {      // 4 k-values per iter
            const unsigned koff = (unsigned)kq * 16u;
            unsigned long long pa[8], pb[8];
            #pragma unroll
            for (int m = 0; m < 8; m++)
                lds_v2u64(pbase + (unsigned)(m * 32 * PITCH) * 4u + koff,
                          pa[m], pb[m]);
            #pragma unroll
            for (int i = 0; i < 8; i++) {
                unsigned long long xa, xb;
                lds_v2u64(xbase + (unsigned)(i * 8 * PITCH) * 4u + koff, xa, xb);
                #pragma unroll
                for (int m = 0; m < 8; m++) {
                    ffma2(acc[i][m], xa, pa[m]);
                    ffma2(acc[i][m], xb, pb[m]);
                }
            }
        }

        // ---- epilogue: combine halves, exp, 2x float4 store per token ----
        #pragma unroll
        for (int i = 0; i < 8; i++) {
            const int t = tg + 8 * i;
            const float dg = sdiag[t];
            float r[8];
            #pragma unroll
            for (int m = 0; m < 8; m++) {
                float lo, hi;
                unpack2(acc[i][m], lo, hi);
                float dd = lo + hi;
                r[m] = RATIO * (__expf(dd - dg) + EPSV);
            }
            float* orow = out + (size_t)(m0 + t) * J + j0;
            *reinterpret_cast<float4*>(orow)     = make_float4(r[0], r[1], r[2], r[3]);
            *reinterpret_cast<float4*>(orow + 4) = make_float4(r[4], r[5], r[6], r[7]);
        }
    }
}

extern "C" void kernel_launch(void* const* d_in, const int* in_sizes, int n_in,
                              void* d_out, int out_size) {
    const float* x    = (const float*)d_in[0];   // [2,16,4096,64] fp32
    const float* proj = (const float*)d_in[1];   // [256,64] fp32
    float* out        = (float*)d_out;           // [2,16,4096,256] fp32

    const int M = in_sizes[0] / D;               // 131072 tokens
    const int n_tiles = M / M_TILE;              // 2048
    const int grid = (n_tiles < GRID) ? n_tiles : GRID;

    const int smem_bytes = (J * PITCH + M_TILE * PITCH + M_TILE) * (int)sizeof(float);
    cudaFuncSetAttribute(performer_kernel,
                         cudaFuncAttributeMaxDynamicSharedMemorySize, smem_bytes);

    performer_kernel<<<grid, THREADS, smem_bytes>>>(x, proj, out, n_tiles);
}

// round 8
// speedup vs baseline: 2.5180x; 2.5180x over previous
#include <cuda_runtime.h>
#include <cuda_bf16.h>

#define J 256
#define D 64
#define M_TILE 128
#define THREADS 512
#define GRID 148

#define OFF_XRAW 0
#define OFF_AHI  32768
#define OFF_ALO  49152
#define OFF_DIAG 65536
#define SMEM_BYTES (OFF_DIAG + 512)

__device__ __forceinline__ unsigned sw128(unsigned off) { return off ^ ((off >> 3) & 0x70u); }

__device__ __forceinline__ unsigned s2u(const void* p) {
    unsigned a;
    asm("{ .reg .u64 t; cvta.to.shared.u64 t, %1; cvt.u32.u64 %0, t; }" : "=r"(a) : "l"(p));
    return a;
}
__device__ __forceinline__ unsigned pk(float a, float b) {
    __nv_bfloat162 t = __floats2bfloat162_rn(a, b);
    return *reinterpret_cast<unsigned*>(&t);
}
__device__ __forceinline__ void ldm_x4(unsigned& r0, unsigned& r1, unsigned& r2, unsigned& r3,
                                       unsigned addr) {
    asm volatile("ldmatrix.sync.aligned.m8n8.x4.shared.b16 {%0,%1,%2,%3}, [%4];"
                 : "=r"(r0), "=r"(r1), "=r"(r2), "=r"(r3) : "r"(addr));
}
__device__ __forceinline__ void mma_bf16(float* d, const unsigned* a, const unsigned* b) {
    asm volatile(
        "mma.sync.aligned.m16n8k16.row.col.f32.bf16.bf16.f32 "
        "{%0,%1,%2,%3}, {%4,%5,%6,%7}, {%8,%9}, {%0,%1,%2,%3};"
        : "+f"(d[0]), "+f"(d[1]), "+f"(d[2]), "+f"(d[3])
        : "r"(a[0]), "r"(a[1]), "r"(a[2]), "r"(a[3]), "r"(b[0]), "r"(b[1]));
}
__device__ __forceinline__ void cp16(unsigned dst, const void* src) {
    asm volatile("cp.async.cg.shared.global [%0], [%1], 16;" :: "r"(dst), "l"(src));
}

__global__ __launch_bounds__(THREADS, 1)
void performer_hmma(const float* __restrict__ x,
                    const float* __restrict__ proj,
                    float* __restrict__ out,
                    int n_tiles) {
    extern __shared__ char smem[];
    const unsigned sb = s2u(smem);
    float* sdiag = reinterpret_cast<float*>(smem + OFF_DIAG);
    const float* xraw = reinterpret_cast<const float*>(smem + OFF_XRAW);

    const int tid = threadIdx.x, lane = tid & 31, w = tid >> 5;

    const float NORM  = 0.3535533905932738f;  // 64^-0.25, folded into B
    const float RATIO = 0.0625f;              // 256^-0.5
    const float EPSV  = 1e-4f;

    // ---- build persistent B fragments from gmem (exact mma layout) ----
    // warp w owns features [w*16, w*16+16): 2 n-tiles of 8.
    // B frag (m16n8k16 col): b0 holds (n=lane>>2, k=2*(lane&3)+{0,1}); b1: k+=8.
    unsigned bh[2][4][2], bl[2][4][2];
    {
        const int n_lo = (w << 4) + (lane >> 2);
        const int kfr  = 2 * (lane & 3);
        #pragma unroll
        for (int nt = 0; nt < 2; nt++) {
            const float* pr = proj + (size_t)(n_lo + nt * 8) * D;
            #pragma unroll
            for (int ks = 0; ks < 4; ks++) {
                #pragma unroll
                for (int h = 0; h < 2; h++) {
                    float a = pr[ks * 16 + h * 8 + kfr]     * NORM;
                    float b = pr[ks * 16 + h * 8 + kfr + 1] * NORM;
                    __nv_bfloat16 ah = __float2bfloat16_rn(a), bh16 = __float2bfloat16_rn(b);
                    bh[nt][ks][h] = pk(__bfloat162float(ah), __bfloat162float(bh16));
                    bl[nt][ks][h] = pk(a - __bfloat162float(ah), b - __bfloat162float(bh16));
                }
            }
        }
    }

    // ---- prefetch first tile's raw x into smem ----
    int tile = blockIdx.x;
    if (tile < n_tiles) {
        const char* src = reinterpret_cast<const char*>(x + (size_t)tile * M_TILE * D);
        #pragma unroll
        for (int r = 0; r < 4; r++) {
            int i = tid + r * THREADS;           // 2048 x 16B = 32 KB
            cp16(sb + OFF_XRAW + i * 16, src + i * 16);
        }
        asm volatile("cp.async.commit_group;" ::: "memory");
    }

    while (tile < n_tiles) {
        const int m0 = tile * M_TILE;
        asm volatile("cp.async.wait_group 0;" ::: "memory");
        __syncthreads();   // xraw ready; previous compute done (A smem safe to overwrite)

        // ---- convert xraw -> A_hi/A_lo bf16 (sw128) + diag ----
        #pragma unroll
        for (int r = 0; r < 2; r++) {
            int i8 = tid + r * THREADS;          // 1024 groups of 8 floats
            int t = i8 >> 3, g = i8 & 7;
            const float4* srcv = reinterpret_cast<const float4*>(xraw + t * D + g * 8);
            float4 v0 = srcv[0], v1 = srcv[1];
            float v[8] = {v0.x, v0.y, v0.z, v0.w, v1.x, v1.y, v1.z, v1.w};
            float s = 0.f;
            unsigned hi[4], lo[4];
            #pragma unroll
            for (int q = 0; q < 4; q++) {
                float a = v[2 * q], b = v[2 * q + 1];
                s += a * a + b * b;
                __nv_bfloat16 ah = __float2bfloat16_rn(a), bh16 = __float2bfloat16_rn(b);
                hi[q] = pk(__bfloat162float(ah), __bfloat162float(bh16));
                lo[q] = pk(a - __bfloat162float(ah), b - __bfloat162float(bh16));
            }
            unsigned off = sw128((unsigned)(t * 128 + g * 16));
            *reinterpret_cast<uint4*>(smem + OFF_AHI + off) = make_uint4(hi[0], hi[1], hi[2], hi[3]);
            *reinterpret_cast<uint4*>(smem + OFF_ALO + off) = make_uint4(lo[0], lo[1], lo[2], lo[3]);
            s += __shfl_xor_sync(0xFFFFFFFFu, s, 1);
            s += __shfl_xor_sync(0xFFFFFFFFu, s, 2);
            s += __shfl_xor_sync(0xFFFFFFFFu, s, 4);
            if ((tid & 7) == 0) sdiag[t] = 0.5f * s;
        }
        __syncthreads();   // A + diag visible; xraw consumed

        // ---- prefetch next tile while computing this one ----
        const int next = tile + GRID;
        if (next < n_tiles) {
            const char* src = reinterpret_cast<const char*>(x + (size_t)next * M_TILE * D);
            #pragma unroll
            for (int r = 0; r < 4; r++) {
                int i = tid + r * THREADS;
                cp16(sb + OFF_XRAW + i * 16, src + i * 16);
            }
            asm volatile("cp.async.commit_group;" ::: "memory");
        }

        // ---- compute: 8 m-tiles of 16 tokens; per warp 2 n-tiles x 4 k x 3 terms ----
        const int rl = lane & 15;
        const unsigned kh = ((unsigned)(lane >> 4)) << 4;
        #pragma unroll
        for (int mt = 0; mt < 8; mt++) {
            float d[2][4] = {{0.f, 0.f, 0.f, 0.f}, {0.f, 0.f, 0.f, 0.f}};
            const unsigned rowoff = (unsigned)((mt * 16 + rl) * 128) + kh;
            #pragma unroll
            for (int ks = 0; ks < 4; ks++) {
                unsigned swo = sw128(rowoff + (unsigned)ks * 32u);
                unsigned ah[4], al[4];
                ldm_x4(ah[0], ah[1], ah[2], ah[3], sb + OFF_AHI + swo);
                ldm_x4(al[0], al[1], al[2], al[3], sb + OFF_ALO + swo);
                #pragma unroll
                for (int nt = 0; nt < 2; nt++) {
                    mma_bf16(d[nt], ah, bh[nt][ks]);
                    mma_bf16(d[nt], ah, bl[nt][ks]);
                    mma_bf16(d[nt], al, bh[nt][ks]);
                }
            }
            // epilogue: D frag rows r0=lane>>2, r0+8; cols 2*(lane&3)+{0,1}
            const int r0  = mt * 16 + (lane >> 2);
            const float dg0 = sdiag[r0], dg1 = sdiag[r0 + 8];
            const int cbase = (w << 4) + 2 * (lane & 3);
            #pragma unroll
            for (int nt = 0; nt < 2; nt++) {
                float2 o0, o1;
                o0.x = RATIO * (__expf(d[nt][0] - dg0) + EPSV);
                o0.y = RATIO * (__expf(d[nt][1] - dg0) + EPSV);
                o1.x = RATIO * (__expf(d[nt][2] - dg1) + EPSV);
                o1.y = RATIO * (__expf(d[nt][3] - dg1) + EPSV);
                const int col = cbase + nt * 8;
                *reinterpret_cast<float2*>(out + (size_t)(m0 + r0) * J + col)     = o0;
                *reinterpret_cast<float2*>(out + (size_t)(m0 + r0 + 8) * J + col) = o1;
            }
        }
        tile = next;
    }
}

extern "C" void kernel_launch(void* const* d_in, const int* in_sizes, int n_in,
                              void* d_out, int out_size) {
    const float* x    = (const float*)d_in[0];   // [2,16,4096,64] fp32
    const float* proj = (const float*)d_in[1];   // [256,64] fp32
    float* out        = (float*)d_out;           // [2,16,4096,256] fp32

    const int M = in_sizes[0] / D;               // 131072 tokens
    const int n_tiles = M / M_TILE;              // 1024
    const int grid = (n_tiles < GRID) ? n_tiles : GRID;

    cudaFuncSetAttribute(performer_hmma,
                         cudaFuncAttributeMaxDynamicSharedMemorySize, SMEM_BYTES);

    performer_hmma<<<grid, THREADS, SMEM_BYTES>>>(x, proj, out, n_tiles);
}

// round 9
// speedup vs baseline: 3.8470x; 1.5278x over previous
#include <cuda_runtime.h>
#include <cuda_bf16.h>

#define J 256
#define D 64
#define M_TILE 128
#define THREADS 256
#define GRID 148

#define OFF_XRAW 0
#define OFF_AHI  32768
#define OFF_ALO  49152
#define OFF_DIAG 65536
#define SMEM_BYTES (OFF_DIAG + 512)

__device__ __forceinline__ unsigned sw128(unsigned off) { return off ^ ((off >> 3) & 0x70u); }

__device__ __forceinline__ unsigned s2u(const void* p) {
    unsigned a;
    asm("{ .reg .u64 t; cvta.to.shared.u64 t, %1; cvt.u32.u64 %0, t; }" : "=r"(a) : "l"(p));
    return a;
}
__device__ __forceinline__ unsigned pk(float a, float b) {
    __nv_bfloat162 t = __floats2bfloat162_rn(a, b);
    return *reinterpret_cast<unsigned*>(&t);
}
__device__ __forceinline__ void ldm_x4(unsigned& r0, unsigned& r1, unsigned& r2, unsigned& r3,
                                       unsigned addr) {
    asm volatile("ldmatrix.sync.aligned.m8n8.x4.shared.b16 {%0,%1,%2,%3}, [%4];"
                 : "=r"(r0), "=r"(r1), "=r"(r2), "=r"(r3) : "r"(addr));
}
__device__ __forceinline__ void mma_bf16(float* d, const unsigned* a, const unsigned* b) {
    asm volatile(
        "mma.sync.aligned.m16n8k16.row.col.f32.bf16.bf16.f32 "
        "{%0,%1,%2,%3}, {%4,%5,%6,%7}, {%8,%9}, {%0,%1,%2,%3};"
        : "+f"(d[0]), "+f"(d[1]), "+f"(d[2]), "+f"(d[3])
        : "r"(a[0]), "r"(a[1]), "r"(a[2]), "r"(a[3]), "r"(b[0]), "r"(b[1]));
}
__device__ __forceinline__ void cp16(unsigned dst, const void* src) {
    asm volatile("cp.async.cg.shared.global [%0], [%1], 16;" :: "r"(dst), "l"(src));
}

__global__ __launch_bounds__(THREADS, 1)
void performer_hmma(const float* __restrict__ x,
                    const float* __restrict__ proj,
                    float* __restrict__ out,
                    int n_tiles) {
    extern __shared__ char smem[];
    const unsigned sb = s2u(smem);
    float* sdiag = reinterpret_cast<float*>(smem + OFF_DIAG);
    const float* xraw = reinterpret_cast<const float*>(smem + OFF_XRAW);

    const int tid = threadIdx.x, lane = tid & 31, w = tid >> 5;
    const int wn = w & 3;        // feature group: 64 features
    const int wm = w >> 2;       // m group: 4 m-tiles (64 tokens)

    const float NORM  = 0.3535533905932738f;  // 64^-0.25, folded into B
    const float RATIO = 0.0625f;              // 256^-0.5
    const float EPSV  = 1e-4f;

    // ---- build persistent B fragments (8 n-tiles x 4 k-steps x hi/lo) ----
    // m16n8k16 col B frag: b0 holds (n=lane>>2, k=2*(lane&3)+{0,1}); b1: k+=8.
    unsigned bh[8][4][2], bl[8][4][2];
    {
        const int n_lo = (wn << 6) + (lane >> 2);
        const int kfr  = 2 * (lane & 3);
        #pragma unroll
        for (int nt = 0; nt < 8; nt++) {
            const float* pr = proj + (size_t)(n_lo + nt * 8) * D;
            #pragma unroll
            for (int ks = 0; ks < 4; ks++) {
                #pragma unroll
                for (int h = 0; h < 2; h++) {
                    float a = pr[ks * 16 + h * 8 + kfr]     * NORM;
                    float b = pr[ks * 16 + h * 8 + kfr + 1] * NORM;
                    __nv_bfloat16 ah = __float2bfloat16_rn(a), bh16 = __float2bfloat16_rn(b);
                    bh[nt][ks][h] = pk(__bfloat162float(ah), __bfloat162float(bh16));
                    bl[nt][ks][h] = pk(a - __bfloat162float(ah), b - __bfloat162float(bh16));
                }
            }
        }
    }

    // ---- prefetch first tile's raw x into smem ----
    int tile = blockIdx.x;
    if (tile < n_tiles) {
        const char* src = reinterpret_cast<const char*>(x + (size_t)tile * M_TILE * D);
        #pragma unroll
        for (int r = 0; r < 8; r++) {
            int i = tid + r * THREADS;           // 2048 x 16B = 32 KB
            cp16(sb + OFF_XRAW + i * 16, src + i * 16);
        }
        asm volatile("cp.async.commit_group;" ::: "memory");
    }

    while (tile < n_tiles) {
        const int m0 = tile * M_TILE;
        asm volatile("cp.async.wait_group 0;" ::: "memory");
        __syncthreads();   // xraw ready; previous compute done

        // ---- convert xraw -> A_hi/A_lo bf16 (sw128) + diag ----
        #pragma unroll
        for (int r = 0; r < 4; r++) {
            int i8 = tid + r * THREADS;          // 1024 groups of 8 floats
            int t = i8 >> 3, g = i8 & 7;
            const float4* srcv = reinterpret_cast<const float4*>(xraw + t * D + g * 8);
            float4 v0 = srcv[0], v1 = srcv[1];
            float v[8] = {v0.x, v0.y, v0.z, v0.w, v1.x, v1.y, v1.z, v1.w};
            float s = 0.f;
            unsigned hi[4], lo[4];
            #pragma unroll
            for (int q = 0; q < 4; q++) {
                float a = v[2 * q], b = v[2 * q + 1];
                s += a * a + b * b;
                __nv_bfloat16 ah = __float2bfloat16_rn(a), bh16 = __float2bfloat16_rn(b);
                hi[q] = pk(__bfloat162float(ah), __bfloat162float(bh16));
                lo[q] = pk(a - __bfloat162float(ah), b - __bfloat162float(bh16));
            }
            unsigned off = sw128((unsigned)(t * 128 + g * 16));
            *reinterpret_cast<uint4*>(smem + OFF_AHI + off) = make_uint4(hi[0], hi[1], hi[2], hi[3]);
            *reinterpret_cast<uint4*>(smem + OFF_ALO + off) = make_uint4(lo[0], lo[1], lo[2], lo[3]);
            s += __shfl_xor_sync(0xFFFFFFFFu, s, 1);
            s += __shfl_xor_sync(0xFFFFFFFFu, s, 2);
            s += __shfl_xor_sync(0xFFFFFFFFu, s, 4);
            if ((tid & 7) == 0) sdiag[t] = 0.5f * s;
        }
        __syncthreads();   // A + diag visible; xraw consumed

        // ---- prefetch next tile while computing this one ----
        const int next = tile + GRID;
        if (next < n_tiles) {
            const char* src = reinterpret_cast<const char*>(x + (size_t)next * M_TILE * D);
            #pragma unroll
            for (int r = 0; r < 8; r++) {
                int i = tid + r * THREADS;
                cp16(sb + OFF_XRAW + i * 16, src + i * 16);
            }
            asm volatile("cp.async.commit_group;" ::: "memory");
        }

        // ---- compute: 4 m-tiles/warp; per mt: 4 ks x (2 ldm + 24 MMA) ----
        const int rl = lane & 15;
        const unsigned kh = ((unsigned)(lane >> 4)) << 4;
        #pragma unroll
        for (int mi = 0; mi < 4; mi++) {
            const int mt = wm * 4 + mi;
            float d[8][4];
            #pragma unroll
            for (int nt = 0; nt < 8; nt++)
                #pragma unroll
                for (int q = 0; q < 4; q++) d[nt][q] = 0.f;

            const unsigned rowoff = (unsigned)((mt * 16 + rl) * 128) + kh;
            #pragma unroll
            for (int ks = 0; ks < 4; ks++) {
                unsigned swo = sw128(rowoff + (unsigned)ks * 32u);
                unsigned ah[4], al[4];
                ldm_x4(ah[0], ah[1], ah[2], ah[3], sb + OFF_AHI + swo);
                ldm_x4(al[0], al[1], al[2], al[3], sb + OFF_ALO + swo);
                #pragma unroll
                for (int nt = 0; nt < 8; nt++) {
                    mma_bf16(d[nt], ah, bh[nt][ks]);
                    mma_bf16(d[nt], ah, bl[nt][ks]);
                    mma_bf16(d[nt], al, bh[nt][ks]);
                }
            }
            // epilogue: D frag rows r0=lane>>2, r0+8; cols 2*(lane&3)+{0,1}
            const int r0  = mt * 16 + (lane >> 2);
            const float dg0 = sdiag[r0], dg1 = sdiag[r0 + 8];
            const int cbase = (wn << 6) + 2 * (lane & 3);
            float* orow0 = out + (size_t)(m0 + r0) * J + cbase;
            float* orow1 = out + (size_t)(m0 + r0 + 8) * J + cbase;
            #pragma unroll
            for (int nt = 0; nt < 8; nt++) {
                float2 o0, o1;
                o0.x = RATIO * (__expf(d[nt][0] - dg0) + EPSV);
                o0.y = RATIO * (__expf(d[nt][1] - dg0) + EPSV);
                o1.x = RATIO * (__expf(d[nt][2] - dg1) + EPSV);
                o1.y = RATIO * (__expf(d[nt][3] - dg1) + EPSV);
                *reinterpret_cast<float2*>(orow0 + nt * 8) = o0;
                *reinterpret_cast<float2*>(orow1 + nt * 8) = o1;
            }
        }
        tile = next;
    }
}

extern "C" void kernel_launch(void* const* d_in, const int* in_sizes, int n_in,
                              void* d_out, int out_size) {
    const float* x    = (const float*)d_in[0];   // [2,16,4096,64] fp32
    const float* proj = (const float*)d_in[1];   // [256,64] fp32
    float* out        = (float*)d_out;           // [2,16,4096,256] fp32

    const int M = in_sizes[0] / D;               // 131072 tokens
    const int n_tiles = M / M_TILE;              // 1024
    const int grid = (n_tiles < GRID) ? n_tiles : GRID;

    cudaFuncSetAttribute(performer_hmma,
                         cudaFuncAttributeMaxDynamicSharedMemorySize, SMEM_BYTES);

    performer_hmma<<<grid, THREADS, SMEM_BYTES>>>(x, proj, out, n_tiles);
}